// round 14
// baseline (speedup 1.0000x reference)
#include <cuda_runtime.h>
#include <cuda_bf16.h>
#include <cstdint>

#define N_INS 8192
#define T_MAX 16
#define HID   256
#define GATES 1024
#define NCLUS 8

__device__ unsigned short g_Tbh[N_INS * T_MAX * HID];
__device__ unsigned short g_Tbl[N_INS * T_MAX * HID];
__device__ unsigned short g_W0h[GATES * HID], g_W0l[GATES * HID];   // Wih_t
__device__ unsigned short g_W1h[GATES * HID], g_W1l[GATES * HID];   // Whh_t
__device__ unsigned short g_W2h[GATES * HID], g_W2l[GATES * HID];   // Wih_i
__device__ unsigned short g_Hh[2][N_INS * HID], g_Hl[2][N_INS * HID];
__device__ float g_C[N_INS * HID];
__device__ float g_G[N_INS * GATES];
__device__ float g_part[NCLUS * N_INS];

#define FMA2(d, a, b) \
    asm("fma.rn.f32x2 %0, %1, %2, %0;" : "+l"(d) : "l"(a), "l"(b))
#define UNPACK2(lo, hi, v) \
    asm("mov.b64 {%0, %1}, %2;" : "=f"(lo), "=f"(hi) : "l"(v))
#define MBAR_WAIT(addr, ph)                                                     \
    asm volatile("{\n\t.reg .pred P;\nWL%=:\n\t"                                \
        "mbarrier.try_wait.parity.acquire.cta.shared::cta.b64 P, [%0], %1, 0x989680;\n\t" \
        "@!P bra WL%=;\n\t}" :: "r"(addr), "r"(ph) : "memory")

__device__ __forceinline__ float fsig(float x) {
    return __fdividef(1.0f, 1.0f + __expf(-x));
}
__device__ __forceinline__ float ftanh_(float x) {
    float e2 = __expf(2.0f * fminf(x, 30.0f));
    return __fdividef(e2 - 1.0f, e2 + 1.0f);
}

// ---- fp32 -> bf16 hi/lo ----
__global__ void __launch_bounds__(256)
conv_pair(const float* __restrict__ in, unsigned short* __restrict__ hi,
          unsigned short* __restrict__ lo, int n4)
{
    int i = blockIdx.x * 256 + threadIdx.x;
    if (i >= n4) return;
    float4 v = reinterpret_cast<const float4*>(in)[i];
    ushort4 h, l;
    float* vp = &v.x;
    unsigned short* hp = &h.x;
    unsigned short* lp = &l.x;
#pragma unroll
    for (int k = 0; k < 4; ++k) {
        __nv_bfloat16 b = __float2bfloat16_rn(vp[k]);
        hp[k] = __bfloat16_as_ushort(b);
        lp[k] = __bfloat16_as_ushort(__float2bfloat16_rn(vp[k] - __bfloat162float(b)));
    }
    reinterpret_cast<ushort4*>(hi)[i] = h;
    reinterpret_cast<ushort4*>(lo)[i] = l;
}

// ---- HMMA primitives (baseline PTX, valid on plain sm_103) ----
__device__ __forceinline__ void ldsm4(uint32_t& r0, uint32_t& r1,
                                      uint32_t& r2, uint32_t& r3, uint32_t addr) {
    asm volatile("ldmatrix.sync.aligned.m8n8.x4.shared.b16 {%0,%1,%2,%3}, [%4];"
                 : "=r"(r0), "=r"(r1), "=r"(r2), "=r"(r3) : "r"(addr));
}
__device__ __forceinline__ void mma16816(float* d, const uint32_t* a,
                                         uint32_t b0, uint32_t b1) {
    asm volatile(
        "mma.sync.aligned.m16n8k16.row.col.f32.bf16.bf16.f32 "
        "{%0,%1,%2,%3}, {%4,%5,%6,%7}, {%8,%9}, {%0,%1,%2,%3};"
        : "+f"(d[0]), "+f"(d[1]), "+f"(d[2]), "+f"(d[3])
        : "r"(a[0]), "r"(a[1]), "r"(a[2]), "r"(a[3]), "r"(b0), "r"(b1));
}

// smem tile pitch: 72 bf16 = 144 B (ldmatrix conflict-free); R12 config, 2 CTA/SM
#define PITCH   144
#define A_BYTES (128 * PITCH)
#define SMEM_SZ (2 * A_BYTES)   // 36864

// ---------------------------------------------------------------------------
// HMMA bf16x3 GEMM — R12 version verbatim (measured best: ~130us/launch,
// rel_err verified). CTA tile 128x128, 8 warps, K in 64-bf16 chunks.
// ---------------------------------------------------------------------------
template<int MODE>
__global__ void __launch_bounds__(256, 2)
gemm_mma(const unsigned short* __restrict__ Ath, const unsigned short* __restrict__ Atl,
         const unsigned short* __restrict__ Hh,  const unsigned short* __restrict__ Hl,
         const unsigned short* __restrict__ W0h, const unsigned short* __restrict__ W0l,
         const unsigned short* __restrict__ W1h, const unsigned short* __restrict__ W1l,
         const int* __restrict__ lengths,
         const float* __restrict__ bih, const float* __restrict__ bhh,
         unsigned short* __restrict__ Hwh, unsigned short* __restrict__ Hwl,
         float* __restrict__ Cs, float* __restrict__ Gout, int t)
{
    extern __shared__ __align__(16) char sm[];
    __shared__ __align__(16) float bs[128];

    const int tid  = threadIdx.x;
    const int wid  = tid >> 5;
    const int lane = tid & 31;
    const int bm   = blockIdx.x * 128;
    const int bn   = blockIdx.y;
    const int wM   = (wid & 3) * 32;
    const int wN   = (wid >> 2) * 64;
    const int NC   = (MODE == 1) ? 24 : 12;

    const uint32_t smA = (uint32_t)__cvta_generic_to_shared(sm);
    const uint32_t smB = smA + A_BYTES;

    if (MODE == 1 && tid < 128) {
        const int wr = (tid & 3) * 256 + bn * 32 + (tid >> 2);
        bs[tid] = bih[wr] + bhh[wr];
    }

    float acc[2][8][4];
#pragma unroll
    for (int i = 0; i < 2; ++i)
#pragma unroll
        for (int j = 0; j < 8; ++j)
#pragma unroll
            for (int k = 0; k < 4; ++k) acc[i][j][k] = 0.0f;

    const uint32_t aoff = (uint32_t)((lane & 15) * PITCH + ((lane >> 4) << 4));
    const uint32_t boff = (uint32_t)(((lane & 7) + ((lane >> 4) << 3)) * PITCH
                                     + (((lane >> 3) & 1) << 4));

    for (int c = 0; c < NC; ++c) {
        const unsigned short *Ap, *Wp;
        size_t strA;
        int kk;
        if (MODE == 1) {
            const int pass = c >> 3, cc = c & 7;
            kk = (cc & 3) * 64;
            if (cc < 4) { Ap = (pass < 2) ? Ath : Atl; strA = T_MAX * HID;
                          Wp = (pass == 1) ? W0l : W0h; }
            else        { Ap = (pass < 2) ? Hh : Hl;   strA = HID;
                          Wp = (pass == 1) ? W1l : W1h; }
        } else {
            const int pass = c >> 2;
            kk = (c & 3) * 64;
            Ap = (pass < 2) ? Hh : Hl; strA = HID;
            Wp = (pass == 1) ? W0l : W0h;
        }

#pragma unroll
        for (int it = 0; it < 4; ++it) {
            const int u = tid + it * 256;
            const int r = u >> 3, k8 = u & 7;
            *reinterpret_cast<uint4*>(sm + r * PITCH + k8 * 16) =
                *reinterpret_cast<const uint4*>(Ap + (size_t)(bm + r) * strA + kk + k8 * 8);
            const int wr = (MODE == 1) ? ((r & 3) * 256 + bn * 32 + (r >> 2))
                                       : (bn * 128 + r);
            *reinterpret_cast<uint4*>(sm + A_BYTES + r * PITCH + k8 * 16) =
                *reinterpret_cast<const uint4*>(Wp + (size_t)wr * HID + kk + k8 * 8);
        }
        __syncthreads();

#pragma unroll
        for (int g = 0; g < 4; ++g) {
            uint32_t a[2][4];
#pragma unroll
            for (int mt = 0; mt < 2; ++mt)
                ldsm4(a[mt][0], a[mt][1], a[mt][2], a[mt][3],
                      smA + (uint32_t)((wM + mt * 16) * PITCH) + aoff + 32 * g);
#pragma unroll
            for (int np = 0; np < 4; ++np) {
                uint32_t b0, b1, b2, b3;
                ldsm4(b0, b1, b2, b3,
                      smB + (uint32_t)((wN + np * 16) * PITCH) + boff + 32 * g);
#pragma unroll
                for (int mt = 0; mt < 2; ++mt) {
                    mma16816(acc[mt][np * 2],     a[mt], b0, b1);
                    mma16816(acc[mt][np * 2 + 1], a[mt], b2, b3);
                }
            }
        }
        __syncthreads();
    }

    if (MODE == 1) {
        const bool odd = (lane & 1);
        const int er   = lane >> 2;
        const int esub = (lane >> 1) & 1;
#pragma unroll
        for (int mt = 0; mt < 2; ++mt) {
            const int m = bm + wM + mt * 16 + er + (odd ? 8 : 0);
            const bool act = (t < lengths[m]);
#pragma unroll
            for (int nt = 0; nt < 8; ++nt) {
                float c0 = acc[mt][nt][0], c1 = acc[mt][nt][1];
                float c2 = acc[mt][nt][2], c3 = acc[mt][nt][3];
                const float x0 = __shfl_xor_sync(0xffffffffu, c0, 1);
                const float x1 = __shfl_xor_sync(0xffffffffu, c1, 1);
                const float x2 = __shfl_xor_sync(0xffffffffu, c2, 1);
                const float x3 = __shfl_xor_sync(0xffffffffu, c3, 1);
                const float gi = odd ? x2 : c0;
                const float gf = odd ? x3 : c1;
                const float gg = odd ? c2 : x0;
                const float go = odd ? c3 : x1;

                const int e_local = (wid >> 2) * 16 + nt * 2 + esub;
                const size_t off = (size_t)m * 256 + bn * 32 + e_local;
                if (act) {
                    const float4 bb = *reinterpret_cast<const float4*>(&bs[4 * e_local]);
                    float cc = Cs[off];
                    cc = fsig(gf + bb.y) * cc + fsig(gi + bb.x) * ftanh_(gg + bb.z);
                    Cs[off] = cc;
                    const float h = fsig(go + bb.w) * ftanh_(cc);
                    const __nv_bfloat16 bh = __float2bfloat16_rn(h);
                    Hwh[off] = __bfloat16_as_ushort(bh);
                    Hwl[off] = __bfloat16_as_ushort(
                        __float2bfloat16_rn(h - __bfloat162float(bh)));
                } else {
                    Hwh[off] = Hh[off];
                    Hwl[off] = Hl[off];
                }
            }
        }
    } else {
        const int er = lane >> 2;
        const int cb = 2 * (lane & 3);
#pragma unroll
        for (int mt = 0; mt < 2; ++mt) {
            const int m = bm + wM + mt * 16 + er;
#pragma unroll
            for (int nt = 0; nt < 8; ++nt) {
                const int col = bn * 128 + wN + nt * 8 + cb;
                *reinterpret_cast<float2*>(Gout + (size_t)m * GATES + col) =
                    make_float2(acc[mt][nt][0], acc[mt][nt][1]);
                *reinterpret_cast<float2*>(Gout + (size_t)(m + 8) * GATES + col) =
                    make_float2(acc[mt][nt][2], acc[mt][nt][3]);
            }
        }
    }
}

// ---------------------------------------------------------------------------
// Serial instruction LSTM — R5 transport (st.async + local parity mbarrier),
// with gate nonlinearities DISTRIBUTED: the q==0 lane of each of 16 warps
// applies fsig/ftanh to its full row pre-activation BEFORE __syncthreads,
// so gs[] holds activated gates and warp0's serial tail is just
// c = sf*c + si*tg; h = so*tanh(c).
// ---------------------------------------------------------------------------
__global__ void __launch_bounds__(512, 1) __cluster_dims__(NCLUS, 1, 1)
ins_lstm(const float* __restrict__ G,
         const float* __restrict__ Whh,
         const float* __restrict__ bih,
         const float* __restrict__ bhh,
         const float* __restrict__ Wl,
         float* __restrict__ part)
{
    __shared__ __align__(16) float hbuf[2][272];
    __shared__ float gs[128];
    __shared__ __align__(8) unsigned long long bar2[2];

    const int tid = threadIdx.x;
    const int cta = blockIdx.x;
    const int r   = tid >> 2;
    const int q   = tid & 3;
    const int gate = r >> 5;                       // 0=i 1=f 2=g 3=o
    const int grow = gate * 256 + cta * 32 + (r & 31);

    unsigned long long w2[32];
#pragma unroll
    for (int jj = 0; jj < 16; ++jj) {
        const float4 v = *reinterpret_cast<const float4*>(
            Whh + (size_t)grow * 256 + q * 64 + jj * 4);
        asm("mov.b64 %0, {%1, %2};" : "=l"(w2[2 * jj])
            : "r"(__float_as_uint(v.x)), "r"(__float_as_uint(v.y)));
        asm("mov.b64 %0, {%1, %2};" : "=l"(w2[2 * jj + 1])
            : "r"(__float_as_uint(v.z)), "r"(__float_as_uint(v.w)));
    }
    const float brow = bih[grow] + bhh[grow];
    const float wl = (tid < 32) ? Wl[cta * 32 + tid] : 0.0f;
    float cst = 0.0f;

    for (int i = tid; i < 2 * 272; i += 512)
        (&hbuf[0][0])[i] = 0.0f;

    const uint32_t hbase = (uint32_t)__cvta_generic_to_shared(&hbuf[0][0]);
    const uint32_t bbase = (uint32_t)__cvta_generic_to_shared(&bar2[0]);

    if (tid == 0) {
        asm volatile("mbarrier.init.shared.b64 [%0], 1;" :: "r"(bbase) : "memory");
        asm volatile("mbarrier.init.shared.b64 [%0], 1;" :: "r"(bbase + 8) : "memory");
        asm volatile("mbarrier.arrive.expect_tx.shared.b64 _, [%0], 1024;"
                     :: "r"(bbase) : "memory");
        asm volatile("mbarrier.arrive.expect_tx.shared.b64 _, [%0], 1024;"
                     :: "r"(bbase + 8) : "memory");
    }

    uint32_t rh[NCLUS], rb[NCLUS];
    {
        const uint32_t coff = (uint32_t)(((cta >> 1) * 68 + (cta & 1) * 32) * 4
                                         + (tid & 15) * 8);
#pragma unroll
        for (int j = 0; j < NCLUS; ++j) {
            uint32_t a, b;
            asm("mapa.shared::cluster.u32 %0, %1, %2;" : "=r"(a) : "r"(hbase), "r"(j));
            asm("mapa.shared::cluster.u32 %0, %1, %2;" : "=r"(b) : "r"(bbase), "r"(j));
            rh[j] = a + coff;
            rb[j] = b;
        }
    }

    __syncthreads();
    asm volatile("barrier.cluster.arrive.aligned;" ::: "memory");
    asm volatile("barrier.cluster.wait.aligned;" ::: "memory");

    float gp0 = 0.0f, gp1 = 0.0f;
    if (q == 0) {
        gp0 = __ldg(&G[grow]);
        gp1 = __ldg(&G[GATES + grow]);
    }

    int php0 = 0, php1 = 0;
    for (int s = 0; s < N_INS; ++s) {
        const int p = s & 1;

        if (s > 0) {
            const uint32_t ba = bbase + (uint32_t)(p * 8);
            const int phx = p ? php1 : php0;
            MBAR_WAIT(ba, phx);
            if (p) php1 ^= 1; else php0 ^= 1;
            if (tid == 0)
                asm volatile("mbarrier.arrive.expect_tx.shared.b64 _, [%0], 1024;"
                             :: "r"(ba) : "memory");
        }

        float gn = 0.0f;
        if (q == 0) {
            const int sn = (s + 2 < N_INS) ? s + 2 : N_INS - 1;
            gn = __ldg(&G[(size_t)sn * GATES + grow]);
        }

        const ulonglong2* hp = reinterpret_cast<const ulonglong2*>(&hbuf[p][q * 68]);
        unsigned long long a2 = 0ULL, b2 = 0ULL;
#pragma unroll
        for (int jj = 0; jj < 16; ++jj) {
            const ulonglong2 hv = hp[jj];
            FMA2(a2, w2[2 * jj],     hv.x);
            FMA2(b2, w2[2 * jj + 1], hv.y);
        }
        float s0, s1, s2, s3;
        UNPACK2(s0, s1, a2);
        UNPACK2(s2, s3, b2);
        float acc = (s0 + s1) + (s2 + s3);
        acc += __shfl_xor_sync(0xffffffffu, acc, 1);
        acc += __shfl_xor_sync(0xffffffffu, acc, 2);
        if (q == 0) {
            // distributed gate activation: gate g gets tanh, i/f/o get sigmoid
            const float full = acc + gp0 + brow;
            gs[r] = (gate == 2) ? ftanh_(full) : fsig(full);
        }
        gp0 = gp1; gp1 = gn;
        __syncthreads();                     // activated gates published

        if (tid < 32) {
            const float si = gs[tid];
            const float sf = gs[32 + tid];
            const float tg = gs[64 + tid];
            const float so = gs[96 + tid];
            cst = sf * cst + si * tg;
            const float h = so * ftanh_(cst);

            const float hlo = __shfl_sync(0xffffffffu, h, (tid & 15) * 2);
            const float hhi = __shfl_sync(0xffffffffu, h, (tid & 15) * 2 + 1);
            if (tid < 16 && s + 1 < N_INS) {
                unsigned long long pkt;
                asm("mov.b64 %0, {%1, %2};" : "=l"(pkt)
                    : "r"(__float_as_uint(hlo)), "r"(__float_as_uint(hhi)));
                const uint32_t bufo = (uint32_t)((p ^ 1) * 272 * 4);
                const uint32_t baro = (uint32_t)((p ^ 1) * 8);
#pragma unroll
                for (int j = 0; j < NCLUS; ++j) {
                    asm volatile(
                        "st.async.shared::cluster.mbarrier::complete_tx::bytes.b64 "
                        "[%0], %1, [%2];"
                        :: "r"(rh[j] + bufo), "l"(pkt), "r"(rb[j] + baro)
                        : "memory");
                }
            }

            float pp = h * wl;
#pragma unroll
            for (int o = 16; o > 0; o >>= 1)
                pp += __shfl_xor_sync(0xffffffffu, pp, o);
            if (tid == 0) part[(size_t)cta * N_INS + s] = pp;
        }
    }
}

__global__ void __launch_bounds__(256)
finalize(float* __restrict__ out, const float* __restrict__ part,
         const float* __restrict__ bl)
{
    const int n = blockIdx.x * 256 + threadIdx.x;
    float s = bl[0];
#pragma unroll
    for (int k = 0; k < NCLUS; ++k) s += part[(size_t)k * N_INS + n];
    out[n] = s;
}

extern "C" void kernel_launch(void* const* d_in, const int* in_sizes, int n_in,
                              void* d_out, int out_size)
{
    const float* tokens = (const float*)d_in[0];
    const int*   lengths= (const int*)  d_in[1];
    const float* Wih_t  = (const float*)d_in[2];
    const float* Whh_t  = (const float*)d_in[3];
    const float* bih_t  = (const float*)d_in[4];
    const float* bhh_t  = (const float*)d_in[5];
    const float* Wih_i  = (const float*)d_in[6];
    const float* Whh_i  = (const float*)d_in[7];
    const float* bih_i  = (const float*)d_in[8];
    const float* bhh_i  = (const float*)d_in[9];
    const float* Wl     = (const float*)d_in[10];
    const float* bl     = (const float*)d_in[11];
    float* out = (float*)d_out;

    unsigned short *Tbh, *Tbl, *W0h, *W0l, *W1h, *W1l, *W2h, *W2l, *Hh, *Hl;
    float *C, *G, *part;
    cudaGetSymbolAddress((void**)&Tbh, g_Tbh);
    cudaGetSymbolAddress((void**)&Tbl, g_Tbl);
    cudaGetSymbolAddress((void**)&W0h, g_W0h);
    cudaGetSymbolAddress((void**)&W0l, g_W0l);
    cudaGetSymbolAddress((void**)&W1h, g_W1h);
    cudaGetSymbolAddress((void**)&W1l, g_W1l);
    cudaGetSymbolAddress((void**)&W2h, g_W2h);
    cudaGetSymbolAddress((void**)&W2l, g_W2l);
    cudaGetSymbolAddress((void**)&Hh,  g_Hh);
    cudaGetSymbolAddress((void**)&Hl,  g_Hl);
    cudaGetSymbolAddress((void**)&C,   g_C);
    cudaGetSymbolAddress((void**)&G,   g_G);
    cudaGetSymbolAddress((void**)&part, g_part);

    const size_t NH = (size_t)N_INS * HID;
    cudaMemsetAsync(C, 0, NH * sizeof(float));
    cudaMemsetAsync(Hh, 0, NH * sizeof(unsigned short));
    cudaMemsetAsync(Hl, 0, NH * sizeof(unsigned short));

    conv_pair<<<(N_INS * T_MAX * HID / 4 + 255) / 256, 256>>>(
        tokens, Tbh, Tbl, N_INS * T_MAX * HID / 4);
    conv_pair<<<(GATES * HID / 4 + 255) / 256, 256>>>(Wih_t, W0h, W0l, GATES * HID / 4);
    conv_pair<<<(GATES * HID / 4 + 255) / 256, 256>>>(Whh_t, W1h, W1l, GATES * HID / 4);
    conv_pair<<<(GATES * HID / 4 + 255) / 256, 256>>>(Wih_i, W2h, W2l, GATES * HID / 4);

    dim3 grid(N_INS / 128, 8);

    for (int t = 0; t < T_MAX; ++t) {
        unsigned short* hrh = Hh + (size_t)(t & 1) * NH;
        unsigned short* hrl = Hl + (size_t)(t & 1) * NH;
        unsigned short* hwh = Hh + (size_t)((t & 1) ^ 1) * NH;
        unsigned short* hwl = Hl + (size_t)((t & 1) ^ 1) * NH;
        gemm_mma<1><<<grid, 256, SMEM_SZ>>>(Tbh + (size_t)t * HID, Tbl + (size_t)t * HID,
                                            hrh, hrl, W0h, W0l, W1h, W1l,
                                            lengths, bih_t, bhh_t,
                                            hwh, hwl, C, nullptr, t);
    }
    // final H in buffer 0
    gemm_mma<0><<<grid, 256, SMEM_SZ>>>(nullptr, nullptr, Hh, Hl,
                                        W2h, W2l, nullptr, nullptr,
                                        nullptr, nullptr, nullptr,
                                        nullptr, nullptr, nullptr, G, 0);

    ins_lstm<<<NCLUS, 512>>>(G, Whh_i, bih_i, bhh_i, Wl, part);
    finalize<<<N_INS / 256, 256>>>(out, part, bl);
}

// round 15
// speedup vs baseline: 1.0547x; 1.0547x over previous
#include <cuda_runtime.h>
#include <cuda_bf16.h>
#include <cstdint>

#define N_INS 8192
#define T_MAX 16
#define HID   256
#define GATES 1024
#define NCLUS 8

__device__ unsigned short g_Tbh[N_INS * T_MAX * HID];
__device__ unsigned short g_Tbl[N_INS * T_MAX * HID];
__device__ unsigned short g_W0h[GATES * HID], g_W0l[GATES * HID];   // Wih_t
__device__ unsigned short g_W1h[GATES * HID], g_W1l[GATES * HID];   // Whh_t
__device__ unsigned short g_W2h[GATES * HID], g_W2l[GATES * HID];   // Wih_i
__device__ unsigned short g_Hh[2][N_INS * HID], g_Hl[2][N_INS * HID];
__device__ float g_C[N_INS * HID];
__device__ float g_G[N_INS * GATES];
__device__ float g_part[NCLUS * N_INS];

#define FMA2(d, a, b) \
    asm("fma.rn.f32x2 %0, %1, %2, %0;" : "+l"(d) : "l"(a), "l"(b))
#define UNPACK2(lo, hi, v) \
    asm("mov.b64 {%0, %1}, %2;" : "=f"(lo), "=f"(hi) : "l"(v))
#define MBAR_WAIT(addr, ph)                                                     \
    asm volatile("{\n\t.reg .pred P;\nWL%=:\n\t"                                \
        "mbarrier.try_wait.parity.acquire.cta.shared::cta.b64 P, [%0], %1, 0x989680;\n\t" \
        "@!P bra WL%=;\n\t}" :: "r"(addr), "r"(ph) : "memory")

__device__ __forceinline__ float fsig(float x) {
    return __fdividef(1.0f, 1.0f + __expf(-x));
}
__device__ __forceinline__ float ftanh_(float x) {
    float e2 = __expf(2.0f * fminf(x, 30.0f));
    return __fdividef(e2 - 1.0f, e2 + 1.0f);
}

// ---- fp32 -> bf16 hi/lo ----
__global__ void __launch_bounds__(256)
conv_pair(const float* __restrict__ in, unsigned short* __restrict__ hi,
          unsigned short* __restrict__ lo, int n4)
{
    int i = blockIdx.x * 256 + threadIdx.x;
    if (i >= n4) return;
    float4 v = reinterpret_cast<const float4*>(in)[i];
    ushort4 h, l;
    float* vp = &v.x;
    unsigned short* hp = &h.x;
    unsigned short* lp = &l.x;
#pragma unroll
    for (int k = 0; k < 4; ++k) {
        __nv_bfloat16 b = __float2bfloat16_rn(vp[k]);
        hp[k] = __bfloat16_as_ushort(b);
        lp[k] = __bfloat16_as_ushort(__float2bfloat16_rn(vp[k] - __bfloat162float(b)));
    }
    reinterpret_cast<ushort4*>(hi)[i] = h;
    reinterpret_cast<ushort4*>(lo)[i] = l;
}

// ---- HMMA primitives (baseline PTX, valid on plain sm_103) ----
__device__ __forceinline__ void ldsm4(uint32_t& r0, uint32_t& r1,
                                      uint32_t& r2, uint32_t& r3, uint32_t addr) {
    asm volatile("ldmatrix.sync.aligned.m8n8.x4.shared.b16 {%0,%1,%2,%3}, [%4];"
                 : "=r"(r0), "=r"(r1), "=r"(r2), "=r"(r3) : "r"(addr));
}
__device__ __forceinline__ void mma16816(float* d, const uint32_t* a,
                                         uint32_t b0, uint32_t b1) {
    asm volatile(
        "mma.sync.aligned.m16n8k16.row.col.f32.bf16.bf16.f32 "
        "{%0,%1,%2,%3}, {%4,%5,%6,%7}, {%8,%9}, {%0,%1,%2,%3};"
        : "+f"(d[0]), "+f"(d[1]), "+f"(d[2]), "+f"(d[3])
        : "r"(a[0]), "r"(a[1]), "r"(a[2]), "r"(a[3]), "r"(b0), "r"(b1));
}
__device__ __forceinline__ void cpa16(uint32_t dst, const void* src) {
    asm volatile("cp.async.cg.shared.global [%0], [%1], 16;"
                 :: "r"(dst), "l"(src) : "memory");
}

// smem tile pitch: 72 bf16 = 144 B (ldmatrix conflict-free).
// K64 chunks double-buffered: 2 x (A 18KB + B 18KB) = 72 KB -> still 2 CTA/SM.
#define PITCH   144
#define A_BYTES (128 * PITCH)          // 18432
#define BUF_SZ  (2 * A_BYTES)          // 36864
#define SMEM_SZ (2 * BUF_SZ)           // 73728

// ---------------------------------------------------------------------------
// HMMA bf16x3 GEMM — R12 math/mapping verbatim, loads via cp.async
// double-buffered (K64 chunks), occupancy preserved at 2 CTA/SM.
// MODE 1: [tok_t|H]@[Wih_t|Whh_t]^T (3 passes, 24 chunks) + fused LSTM epi.
// MODE 0: H@Wih_i^T (12 chunks) -> G.
// ---------------------------------------------------------------------------
template<int MODE>
__global__ void __launch_bounds__(256, 2)
gemm_mma(const unsigned short* __restrict__ Ath, const unsigned short* __restrict__ Atl,
         const unsigned short* __restrict__ Hh,  const unsigned short* __restrict__ Hl,
         const unsigned short* __restrict__ W0h, const unsigned short* __restrict__ W0l,
         const unsigned short* __restrict__ W1h, const unsigned short* __restrict__ W1l,
         const int* __restrict__ lengths,
         const float* __restrict__ bih, const float* __restrict__ bhh,
         unsigned short* __restrict__ Hwh, unsigned short* __restrict__ Hwl,
         float* __restrict__ Cs, float* __restrict__ Gout, int t)
{
    extern __shared__ __align__(16) char sm[];
    __shared__ __align__(16) float bs[128];

    const int tid  = threadIdx.x;
    const int wid  = tid >> 5;
    const int lane = tid & 31;
    const int bm   = blockIdx.x * 128;
    const int bn   = blockIdx.y;
    const int wM   = (wid & 3) * 32;
    const int wN   = (wid >> 2) * 64;
    const int NC   = (MODE == 1) ? 24 : 12;

    const uint32_t smBase = (uint32_t)__cvta_generic_to_shared(sm);

    if (MODE == 1 && tid < 128) {
        const int wr = (tid & 3) * 256 + bn * 32 + (tid >> 2);
        bs[tid] = bih[wr] + bhh[wr];
    }

    float acc[2][8][4];
#pragma unroll
    for (int i = 0; i < 2; ++i)
#pragma unroll
        for (int j = 0; j < 8; ++j)
#pragma unroll
            for (int k = 0; k < 4; ++k) acc[i][j][k] = 0.0f;

    const uint32_t aoff = (uint32_t)((lane & 15) * PITCH + ((lane >> 4) << 4));
    const uint32_t boff = (uint32_t)(((lane & 7) + ((lane >> 4) << 3)) * PITCH
                                     + (((lane >> 3) & 1) << 4));

    // issue chunk c's loads into buffer `buf` via cp.async (8 x 16B per thread)
    auto issue_chunk = [&](int c, int buf) {
        const unsigned short *Ap, *Wp;
        size_t strA;
        int kk;
        if (MODE == 1) {
            const int pass = c >> 3, cc = c & 7;
            kk = (cc & 3) * 64;
            if (cc < 4) { Ap = (pass < 2) ? Ath : Atl; strA = T_MAX * HID;
                          Wp = (pass == 1) ? W0l : W0h; }
            else        { Ap = (pass < 2) ? Hh : Hl;   strA = HID;
                          Wp = (pass == 1) ? W1l : W1h; }
        } else {
            const int pass = c >> 2;
            kk = (c & 3) * 64;
            Ap = (pass < 2) ? Hh : Hl; strA = HID;
            Wp = (pass == 1) ? W0l : W0h;
        }
        const uint32_t base = smBase + (uint32_t)(buf * BUF_SZ);
#pragma unroll
        for (int it = 0; it < 4; ++it) {
            const int u = tid + it * 256;       // 0..1023
            const int r = u >> 3, k8 = u & 7;
            cpa16(base + (uint32_t)(r * PITCH + k8 * 16),
                  Ap + (size_t)(bm + r) * strA + kk + k8 * 8);
            const int wr = (MODE == 1) ? ((r & 3) * 256 + bn * 32 + (r >> 2))
                                       : (bn * 128 + r);
            cpa16(base + (uint32_t)(A_BYTES + r * PITCH + k8 * 16),
                  Wp + (size_t)wr * HID + kk + k8 * 8);
        }
        asm volatile("cp.async.commit_group;" ::: "memory");
    };

    issue_chunk(0, 0);

    for (int c = 0; c < NC; ++c) {
        const int buf = c & 1;
        if (c + 1 < NC) {
            issue_chunk(c + 1, buf ^ 1);        // buf^1 last read at iter c-1
            asm volatile("cp.async.wait_group 1;" ::: "memory");
        } else {
            asm volatile("cp.async.wait_group 0;" ::: "memory");
        }
        __syncthreads();

        const uint32_t tA = smBase + (uint32_t)(buf * BUF_SZ);
        const uint32_t tB = tA + A_BYTES;
#pragma unroll
        for (int g = 0; g < 4; ++g) {
            uint32_t a[2][4];
#pragma unroll
            for (int mt = 0; mt < 2; ++mt)
                ldsm4(a[mt][0], a[mt][1], a[mt][2], a[mt][3],
                      tA + (uint32_t)((wM + mt * 16) * PITCH) + aoff + 32 * g);
#pragma unroll
            for (int np = 0; np < 4; ++np) {
                uint32_t b0, b1, b2, b3;
                ldsm4(b0, b1, b2, b3,
                      tB + (uint32_t)((wN + np * 16) * PITCH) + boff + 32 * g);
#pragma unroll
                for (int mt = 0; mt < 2; ++mt) {
                    mma16816(acc[mt][np * 2],     a[mt], b0, b1);
                    mma16816(acc[mt][np * 2 + 1], a[mt], b2, b3);
                }
            }
        }
        __syncthreads();   // all reads of `buf` done before it's re-issued
    }

    if (MODE == 1) {
        const bool odd = (lane & 1);
        const int er   = lane >> 2;
        const int esub = (lane >> 1) & 1;
#pragma unroll
        for (int mt = 0; mt < 2; ++mt) {
            const int m = bm + wM + mt * 16 + er + (odd ? 8 : 0);
            const bool act = (t < lengths[m]);
#pragma unroll
            for (int nt = 0; nt < 8; ++nt) {
                float c0 = acc[mt][nt][0], c1 = acc[mt][nt][1];
                float c2 = acc[mt][nt][2], c3 = acc[mt][nt][3];
                const float x0 = __shfl_xor_sync(0xffffffffu, c0, 1);
                const float x1 = __shfl_xor_sync(0xffffffffu, c1, 1);
                const float x2 = __shfl_xor_sync(0xffffffffu, c2, 1);
                const float x3 = __shfl_xor_sync(0xffffffffu, c3, 1);
                const float gi = odd ? x2 : c0;
                const float gf = odd ? x3 : c1;
                const float gg = odd ? c2 : x0;
                const float go = odd ? c3 : x1;

                const int e_local = (wid >> 2) * 16 + nt * 2 + esub;
                const size_t off = (size_t)m * 256 + bn * 32 + e_local;
                if (act) {
                    const float4 bb = *reinterpret_cast<const float4*>(&bs[4 * e_local]);
                    float cc = Cs[off];
                    cc = fsig(gf + bb.y) * cc + fsig(gi + bb.x) * ftanh_(gg + bb.z);
                    Cs[off] = cc;
                    const float h = fsig(go + bb.w) * ftanh_(cc);
                    const __nv_bfloat16 bh = __float2bfloat16_rn(h);
                    Hwh[off] = __bfloat16_as_ushort(bh);
                    Hwl[off] = __bfloat16_as_ushort(
                        __float2bfloat16_rn(h - __bfloat162float(bh)));
                } else {
                    Hwh[off] = Hh[off];
                    Hwl[off] = Hl[off];
                }
            }
        }
    } else {
        const int er = lane >> 2;
        const int cb = 2 * (lane & 3);
#pragma unroll
        for (int mt = 0; mt < 2; ++mt) {
            const int m = bm + wM + mt * 16 + er;
#pragma unroll
            for (int nt = 0; nt < 8; ++nt) {
                const int col = bn * 128 + wN + nt * 8 + cb;
                *reinterpret_cast<float2*>(Gout + (size_t)m * GATES + col) =
                    make_float2(acc[mt][nt][0], acc[mt][nt][1]);
                *reinterpret_cast<float2*>(Gout + (size_t)(m + 8) * GATES + col) =
                    make_float2(acc[mt][nt][2], acc[mt][nt][3]);
            }
        }
    }
}

// ---------------------------------------------------------------------------
// Serial instruction LSTM — R5/R12 structure verbatim (best measured).
// ---------------------------------------------------------------------------
__global__ void __launch_bounds__(512, 1) __cluster_dims__(NCLUS, 1, 1)
ins_lstm(const float* __restrict__ G,
         const float* __restrict__ Whh,
         const float* __restrict__ bih,
         const float* __restrict__ bhh,
         const float* __restrict__ Wl,
         float* __restrict__ part)
{
    __shared__ __align__(16) float hbuf[2][272];
    __shared__ float gs[128];
    __shared__ __align__(8) unsigned long long bar2[2];

    const int tid = threadIdx.x;
    const int cta = blockIdx.x;
    const int r   = tid >> 2;
    const int q   = tid & 3;
    const int grow = (r >> 5) * 256 + cta * 32 + (r & 31);

    unsigned long long w2[32];
#pragma unroll
    for (int jj = 0; jj < 16; ++jj) {
        const float4 v = *reinterpret_cast<const float4*>(
            Whh + (size_t)grow * 256 + q * 64 + jj * 4);
        asm("mov.b64 %0, {%1, %2};" : "=l"(w2[2 * jj])
            : "r"(__float_as_uint(v.x)), "r"(__float_as_uint(v.y)));
        asm("mov.b64 %0, {%1, %2};" : "=l"(w2[2 * jj + 1])
            : "r"(__float_as_uint(v.z)), "r"(__float_as_uint(v.w)));
    }
    const float brow = bih[grow] + bhh[grow];
    const float wl = (tid < 32) ? Wl[cta * 32 + tid] : 0.0f;
    float cst = 0.0f;

    for (int i = tid; i < 2 * 272; i += 512)
        (&hbuf[0][0])[i] = 0.0f;

    const uint32_t hbase = (uint32_t)__cvta_generic_to_shared(&hbuf[0][0]);
    const uint32_t bbase = (uint32_t)__cvta_generic_to_shared(&bar2[0]);

    if (tid == 0) {
        asm volatile("mbarrier.init.shared.b64 [%0], 1;" :: "r"(bbase) : "memory");
        asm volatile("mbarrier.init.shared.b64 [%0], 1;" :: "r"(bbase + 8) : "memory");
        asm volatile("mbarrier.arrive.expect_tx.shared.b64 _, [%0], 1024;"
                     :: "r"(bbase) : "memory");
        asm volatile("mbarrier.arrive.expect_tx.shared.b64 _, [%0], 1024;"
                     :: "r"(bbase + 8) : "memory");
    }

    uint32_t rh[NCLUS], rb[NCLUS];
    {
        const uint32_t coff = (uint32_t)(((cta >> 1) * 68 + (cta & 1) * 32) * 4
                                         + (tid & 15) * 8);
#pragma unroll
        for (int j = 0; j < NCLUS; ++j) {
            uint32_t a, b;
            asm("mapa.shared::cluster.u32 %0, %1, %2;" : "=r"(a) : "r"(hbase), "r"(j));
            asm("mapa.shared::cluster.u32 %0, %1, %2;" : "=r"(b) : "r"(bbase), "r"(j));
            rh[j] = a + coff;
            rb[j] = b;
        }
    }

    __syncthreads();
    asm volatile("barrier.cluster.arrive.aligned;" ::: "memory");
    asm volatile("barrier.cluster.wait.aligned;" ::: "memory");

    float gp0 = 0.0f, gp1 = 0.0f;
    if (q == 0) {
        gp0 = __ldg(&G[grow]);
        gp1 = __ldg(&G[GATES + grow]);
    }

    int php0 = 0, php1 = 0;
    for (int s = 0; s < N_INS; ++s) {
        const int p = s & 1;

        if (s > 0) {
            const uint32_t ba = bbase + (uint32_t)(p * 8);
            const int phx = p ? php1 : php0;
            MBAR_WAIT(ba, phx);
            if (p) php1 ^= 1; else php0 ^= 1;
            if (tid == 0)
                asm volatile("mbarrier.arrive.expect_tx.shared.b64 _, [%0], 1024;"
                             :: "r"(ba) : "memory");
        }

        float gn = 0.0f;
        if (q == 0) {
            const int sn = (s + 2 < N_INS) ? s + 2 : N_INS - 1;
            gn = __ldg(&G[(size_t)sn * GATES + grow]);
        }

        const ulonglong2* hp = reinterpret_cast<const ulonglong2*>(&hbuf[p][q * 68]);
        unsigned long long a2 = 0ULL, b2 = 0ULL;
#pragma unroll
        for (int jj = 0; jj < 16; ++jj) {
            const ulonglong2 hv = hp[jj];
            FMA2(a2, w2[2 * jj],     hv.x);
            FMA2(b2, w2[2 * jj + 1], hv.y);
        }
        float s0, s1, s2, s3;
        UNPACK2(s0, s1, a2);
        UNPACK2(s2, s3, b2);
        float acc = (s0 + s1) + (s2 + s3);
        acc += __shfl_xor_sync(0xffffffffu, acc, 1);
        acc += __shfl_xor_sync(0xffffffffu, acc, 2);
        if (q == 0) gs[r] = acc + gp0 + brow;
        gp0 = gp1; gp1 = gn;
        __syncthreads();

        if (tid < 32) {
            const float gi = gs[tid];
            const float gf = gs[32 + tid];
            const float gg = gs[64 + tid];
            const float go = gs[96 + tid];
            cst = fsig(gf) * cst + fsig(gi) * ftanh_(gg);
            const float h = fsig(go) * ftanh_(cst);

            const float hlo = __shfl_sync(0xffffffffu, h, (tid & 15) * 2);
            const float hhi = __shfl_sync(0xffffffffu, h, (tid & 15) * 2 + 1);
            if (tid < 16 && s + 1 < N_INS) {
                unsigned long long pkt;
                asm("mov.b64 %0, {%1, %2};" : "=l"(pkt)
                    : "r"(__float_as_uint(hlo)), "r"(__float_as_uint(hhi)));
                const uint32_t bufo = (uint32_t)((p ^ 1) * 272 * 4);
                const uint32_t baro = (uint32_t)((p ^ 1) * 8);
#pragma unroll
                for (int j = 0; j < NCLUS; ++j) {
                    asm volatile(
                        "st.async.shared::cluster.mbarrier::complete_tx::bytes.b64 "
                        "[%0], %1, [%2];"
                        :: "r"(rh[j] + bufo), "l"(pkt), "r"(rb[j] + baro)
                        : "memory");
                }
            }

            float pp = h * wl;
#pragma unroll
            for (int o = 16; o > 0; o >>= 1)
                pp += __shfl_xor_sync(0xffffffffu, pp, o);
            if (tid == 0) part[(size_t)cta * N_INS + s] = pp;
        }
    }
}

__global__ void __launch_bounds__(256)
finalize(float* __restrict__ out, const float* __restrict__ part,
         const float* __restrict__ bl)
{
    const int n = blockIdx.x * 256 + threadIdx.x;
    float s = bl[0];
#pragma unroll
    for (int k = 0; k < NCLUS; ++k) s += part[(size_t)k * N_INS + n];
    out[n] = s;
}

extern "C" void kernel_launch(void* const* d_in, const int* in_sizes, int n_in,
                              void* d_out, int out_size)
{
    const float* tokens = (const float*)d_in[0];
    const int*   lengths= (const int*)  d_in[1];
    const float* Wih_t  = (const float*)d_in[2];
    const float* Whh_t  = (const float*)d_in[3];
    const float* bih_t  = (const float*)d_in[4];
    const float* bhh_t  = (const float*)d_in[5];
    const float* Wih_i  = (const float*)d_in[6];
    const float* Whh_i  = (const float*)d_in[7];
    const float* bih_i  = (const float*)d_in[8];
    const float* bhh_i  = (const float*)d_in[9];
    const float* Wl     = (const float*)d_in[10];
    const float* bl     = (const float*)d_in[11];
    float* out = (float*)d_out;

    unsigned short *Tbh, *Tbl, *W0h, *W0l, *W1h, *W1l, *W2h, *W2l, *Hh, *Hl;
    float *C, *G, *part;
    cudaGetSymbolAddress((void**)&Tbh, g_Tbh);
    cudaGetSymbolAddress((void**)&Tbl, g_Tbl);
    cudaGetSymbolAddress((void**)&W0h, g_W0h);
    cudaGetSymbolAddress((void**)&W0l, g_W0l);
    cudaGetSymbolAddress((void**)&W1h, g_W1h);
    cudaGetSymbolAddress((void**)&W1l, g_W1l);
    cudaGetSymbolAddress((void**)&W2h, g_W2h);
    cudaGetSymbolAddress((void**)&W2l, g_W2l);
    cudaGetSymbolAddress((void**)&Hh,  g_Hh);
    cudaGetSymbolAddress((void**)&Hl,  g_Hl);
    cudaGetSymbolAddress((void**)&C,   g_C);
    cudaGetSymbolAddress((void**)&G,   g_G);
    cudaGetSymbolAddress((void**)&part, g_part);

    cudaFuncSetAttribute(gemm_mma<1>, cudaFuncAttributeMaxDynamicSharedMemorySize, SMEM_SZ);
    cudaFuncSetAttribute(gemm_mma<0>, cudaFuncAttributeMaxDynamicSharedMemorySize, SMEM_SZ);

    const size_t NH = (size_t)N_INS * HID;
    cudaMemsetAsync(C, 0, NH * sizeof(float));
    cudaMemsetAsync(Hh, 0, NH * sizeof(unsigned short));
    cudaMemsetAsync(Hl, 0, NH * sizeof(unsigned short));

    conv_pair<<<(N_INS * T_MAX * HID / 4 + 255) / 256, 256>>>(
        tokens, Tbh, Tbl, N_INS * T_MAX * HID / 4);
    conv_pair<<<(GATES * HID / 4 + 255) / 256, 256>>>(Wih_t, W0h, W0l, GATES * HID / 4);
    conv_pair<<<(GATES * HID / 4 + 255) / 256, 256>>>(Whh_t, W1h, W1l, GATES * HID / 4);
    conv_pair<<<(GATES * HID / 4 + 255) / 256, 256>>>(Wih_i, W2h, W2l, GATES * HID / 4);

    dim3 grid(N_INS / 128, 8);

    for (int t = 0; t < T_MAX; ++t) {
        unsigned short* hrh = Hh + (size_t)(t & 1) * NH;
        unsigned short* hrl = Hl + (size_t)(t & 1) * NH;
        unsigned short* hwh = Hh + (size_t)((t & 1) ^ 1) * NH;
        unsigned short* hwl = Hl + (size_t)((t & 1) ^ 1) * NH;
        gemm_mma<1><<<grid, 256, SMEM_SZ>>>(Tbh + (size_t)t * HID, Tbl + (size_t)t * HID,
                                            hrh, hrl, W0h, W0l, W1h, W1l,
                                            lengths, bih_t, bhh_t,
                                            hwh, hwl, C, nullptr, t);
    }
    // final H in buffer 0
    gemm_mma<0><<<grid, 256, SMEM_SZ>>>(nullptr, nullptr, Hh, Hl,
                                        W2h, W2l, nullptr, nullptr,
                                        nullptr, nullptr, nullptr,
                                        nullptr, nullptr, nullptr, G, 0);

    ins_lstm<<<NCLUS, 512>>>(G, Whh_i, bih_i, bhh_i, Wl, part);
    finalize<<<N_INS / 256, 256>>>(out, part, bl);
}

// round 16
// speedup vs baseline: 1.0829x; 1.0268x over previous
#include <cuda_runtime.h>
#include <cuda_bf16.h>
#include <cstdint>

#define N_INS 8192
#define T_MAX 16
#define HID   256
#define GATES 1024
#define NCLUS 8

__device__ unsigned short g_Tbh[N_INS * T_MAX * HID];
__device__ unsigned short g_Tbl[N_INS * T_MAX * HID];
__device__ unsigned short g_W0h[GATES * HID], g_W0l[GATES * HID];   // Wih_t
__device__ unsigned short g_W1h[GATES * HID], g_W1l[GATES * HID];   // Whh_t
__device__ unsigned short g_W2h[GATES * HID], g_W2l[GATES * HID];   // Wih_i
__device__ unsigned short g_Hh[2][N_INS * HID], g_Hl[2][N_INS * HID];
__device__ float g_C[N_INS * HID];
__device__ float g_G[N_INS * GATES];
__device__ float g_part[NCLUS * N_INS];

#define FMA2(d, a, b) \
    asm("fma.rn.f32x2 %0, %1, %2, %0;" : "+l"(d) : "l"(a), "l"(b))
#define UNPACK2(lo, hi, v) \
    asm("mov.b64 {%0, %1}, %2;" : "=f"(lo), "=f"(hi) : "l"(v))
#define MBAR_WAIT(addr, ph)                                                     \
    asm volatile("{\n\t.reg .pred P;\nWL%=:\n\t"                                \
        "mbarrier.try_wait.parity.acquire.cta.shared::cta.b64 P, [%0], %1, 0x989680;\n\t" \
        "@!P bra WL%=;\n\t}" :: "r"(addr), "r"(ph) : "memory")

__device__ __forceinline__ float fsig(float x) {
    return __fdividef(1.0f, 1.0f + __expf(-x));
}
__device__ __forceinline__ float ftanh_(float x) {
    float e2 = __expf(2.0f * fminf(x, 30.0f));
    return __fdividef(e2 - 1.0f, e2 + 1.0f);
}

// ---- fp32 -> bf16 hi/lo ----
__global__ void __launch_bounds__(256)
conv_pair(const float* __restrict__ in, unsigned short* __restrict__ hi,
          unsigned short* __restrict__ lo, int n4)
{
    int i = blockIdx.x * 256 + threadIdx.x;
    if (i >= n4) return;
    float4 v = reinterpret_cast<const float4*>(in)[i];
    ushort4 h, l;
    float* vp = &v.x;
    unsigned short* hp = &h.x;
    unsigned short* lp = &l.x;
#pragma unroll
    for (int k = 0; k < 4; ++k) {
        __nv_bfloat16 b = __float2bfloat16_rn(vp[k]);
        hp[k] = __bfloat16_as_ushort(b);
        lp[k] = __bfloat16_as_ushort(__float2bfloat16_rn(vp[k] - __bfloat162float(b)));
    }
    reinterpret_cast<ushort4*>(hi)[i] = h;
    reinterpret_cast<ushort4*>(lo)[i] = l;
}

// ---- HMMA primitives (baseline PTX, valid on plain sm_103) ----
__device__ __forceinline__ void ldsm4(uint32_t& r0, uint32_t& r1,
                                      uint32_t& r2, uint32_t& r3, uint32_t addr) {
    asm volatile("ldmatrix.sync.aligned.m8n8.x4.shared.b16 {%0,%1,%2,%3}, [%4];"
                 : "=r"(r0), "=r"(r1), "=r"(r2), "=r"(r3) : "r"(addr));
}
__device__ __forceinline__ void mma16816(float* d, const uint32_t* a,
                                         uint32_t b0, uint32_t b1) {
    asm volatile(
        "mma.sync.aligned.m16n8k16.row.col.f32.bf16.bf16.f32 "
        "{%0,%1,%2,%3}, {%4,%5,%6,%7}, {%8,%9}, {%0,%1,%2,%3};"
        : "+f"(d[0]), "+f"(d[1]), "+f"(d[2]), "+f"(d[3])
        : "r"(a[0]), "r"(a[1]), "r"(a[2]), "r"(a[3]), "r"(b0), "r"(b1));
}
__device__ __forceinline__ void cpa16(uint32_t dst, const void* src) {
    asm volatile("cp.async.cg.shared.global [%0], [%1], 16;"
                 :: "r"(dst), "l"(src) : "memory");
}

// smem: 4 tiles (Ah, Al, Wh, Wl), each 128 rows x 64 bf16 @ pitch 144B.
// 4 x 18432 = 73728 -> 2 CTA/SM preserved.
#define PITCH   144
#define TILE    (128 * PITCH)          // 18432
#define SMEM_SZ (4 * TILE)             // 73728

// ---------------------------------------------------------------------------
// HMMA bf16x3 GEMM with GROUPED loads: per (part, kslice) group, load
// Ah/Al/Wh/Wl once and run the 3 passes (Ah*Wh, Ah*Wl, Al*Wh) against the
// resident tiles. 33% fewer gmem load ops than R15 (the measured bottleneck).
// Fragment math / column mapping / epilogue identical to the verified R12.
// MODE 1: [tok_t|H]@[Wih_t|Whh_t]^T (8 groups) + fused LSTM epilogue.
// MODE 0: H@Wih_i^T (4 groups) -> G.
// ---------------------------------------------------------------------------
template<int MODE>
__global__ void __launch_bounds__(256, 2)
gemm_mma(const unsigned short* __restrict__ Ath, const unsigned short* __restrict__ Atl,
         const unsigned short* __restrict__ Hh,  const unsigned short* __restrict__ Hl,
         const unsigned short* __restrict__ W0h, const unsigned short* __restrict__ W0l,
         const unsigned short* __restrict__ W1h, const unsigned short* __restrict__ W1l,
         const int* __restrict__ lengths,
         const float* __restrict__ bih, const float* __restrict__ bhh,
         unsigned short* __restrict__ Hwh, unsigned short* __restrict__ Hwl,
         float* __restrict__ Cs, float* __restrict__ Gout, int t)
{
    extern __shared__ __align__(16) char sm[];
    __shared__ __align__(16) float bs[128];

    const int tid  = threadIdx.x;
    const int wid  = tid >> 5;
    const int lane = tid & 31;
    const int bm   = blockIdx.x * 128;
    const int bn   = blockIdx.y;
    const int wM   = (wid & 3) * 32;
    const int wN   = (wid >> 2) * 64;
    const int NG   = (MODE == 1) ? 8 : 4;

    const uint32_t smBase = (uint32_t)__cvta_generic_to_shared(sm);

    if (MODE == 1 && tid < 128) {
        const int wr = (tid & 3) * 256 + bn * 32 + (tid >> 2);
        bs[tid] = bih[wr] + bhh[wr];
    }

    float acc[2][8][4];
#pragma unroll
    for (int i = 0; i < 2; ++i)
#pragma unroll
        for (int j = 0; j < 8; ++j)
#pragma unroll
            for (int k = 0; k < 4; ++k) acc[i][j][k] = 0.0f;

    const uint32_t aoff = (uint32_t)((lane & 15) * PITCH + ((lane >> 4) << 4));
    const uint32_t boff = (uint32_t)(((lane & 7) + ((lane >> 4) << 3)) * PITCH
                                     + (((lane >> 3) & 1) << 4));

    for (int gi = 0; gi < NG; ++gi) {
        // resolve group sources
        const unsigned short *Ah_, *Al_, *Wh_, *Wl_;
        size_t strA;
        int kk;
        if (MODE == 1) {
            const int part = gi >> 2;
            kk = (gi & 3) * 64;
            if (part == 0) { Ah_ = Ath; Al_ = Atl; strA = T_MAX * HID;
                             Wh_ = W0h; Wl_ = W0l; }
            else           { Ah_ = Hh;  Al_ = Hl;  strA = HID;
                             Wh_ = W1h; Wl_ = W1l; }
        } else {
            kk = gi * 64;
            Ah_ = Hh; Al_ = Hl; strA = HID;
            Wh_ = W0h; Wl_ = W0l;
        }

        // load 4 tiles via cp.async (16 ops/thread); buffers are free:
        // previous group's MMA is followed by the loop-end __syncthreads.
        {
            // A-hi tile @0
#pragma unroll
            for (int it = 0; it < 4; ++it) {
                const int u = tid + it * 256;
                const int r = u >> 3, k8 = u & 7;
                cpa16(smBase + (uint32_t)(r * PITCH + k8 * 16),
                      Ah_ + (size_t)(bm + r) * strA + kk + k8 * 8);
            }
            // A-lo tile @TILE
#pragma unroll
            for (int it = 0; it < 4; ++it) {
                const int u = tid + it * 256;
                const int r = u >> 3, k8 = u & 7;
                cpa16(smBase + (uint32_t)(TILE + r * PITCH + k8 * 16),
                      Al_ + (size_t)(bm + r) * strA + kk + k8 * 8);
            }
            // W-hi tile @2*TILE
#pragma unroll
            for (int it = 0; it < 4; ++it) {
                const int u = tid + it * 256;
                const int r = u >> 3, k8 = u & 7;
                const int wr = (MODE == 1) ? ((r & 3) * 256 + bn * 32 + (r >> 2))
                                           : (bn * 128 + r);
                cpa16(smBase + (uint32_t)(2 * TILE + r * PITCH + k8 * 16),
                      Wh_ + (size_t)wr * HID + kk + k8 * 8);
            }
            // W-lo tile @3*TILE
#pragma unroll
            for (int it = 0; it < 4; ++it) {
                const int u = tid + it * 256;
                const int r = u >> 3, k8 = u & 7;
                const int wr = (MODE == 1) ? ((r & 3) * 256 + bn * 32 + (r >> 2))
                                           : (bn * 128 + r);
                cpa16(smBase + (uint32_t)(3 * TILE + r * PITCH + k8 * 16),
                      Wl_ + (size_t)wr * HID + kk + k8 * 8);
            }
            asm volatile("cp.async.commit_group;" ::: "memory");
            asm volatile("cp.async.wait_group 0;" ::: "memory");
            __syncthreads();
        }

        const uint32_t tAh = smBase;
        const uint32_t tAl = smBase + TILE;
        const uint32_t tWh = smBase + 2 * TILE;
        const uint32_t tWl = smBase + 3 * TILE;

#pragma unroll
        for (int g = 0; g < 4; ++g) {
            uint32_t a[2][4];
            // A-hi fragments, used against BOTH Wh and Wl
#pragma unroll
            for (int mt = 0; mt < 2; ++mt)
                ldsm4(a[mt][0], a[mt][1], a[mt][2], a[mt][3],
                      tAh + (uint32_t)((wM + mt * 16) * PITCH) + aoff + 32 * g);
#pragma unroll
            for (int np = 0; np < 4; ++np) {
                uint32_t b0, b1, b2, b3;
                ldsm4(b0, b1, b2, b3,
                      tWh + (uint32_t)((wN + np * 16) * PITCH) + boff + 32 * g);
#pragma unroll
                for (int mt = 0; mt < 2; ++mt) {
                    mma16816(acc[mt][np * 2],     a[mt], b0, b1);
                    mma16816(acc[mt][np * 2 + 1], a[mt], b2, b3);
                }
                ldsm4(b0, b1, b2, b3,
                      tWl + (uint32_t)((wN + np * 16) * PITCH) + boff + 32 * g);
#pragma unroll
                for (int mt = 0; mt < 2; ++mt) {
                    mma16816(acc[mt][np * 2],     a[mt], b0, b1);
                    mma16816(acc[mt][np * 2 + 1], a[mt], b2, b3);
                }
            }
            // A-lo fragments against Wh only
#pragma unroll
            for (int mt = 0; mt < 2; ++mt)
                ldsm4(a[mt][0], a[mt][1], a[mt][2], a[mt][3],
                      tAl + (uint32_t)((wM + mt * 16) * PITCH) + aoff + 32 * g);
#pragma unroll
            for (int np = 0; np < 4; ++np) {
                uint32_t b0, b1, b2, b3;
                ldsm4(b0, b1, b2, b3,
                      tWh + (uint32_t)((wN + np * 16) * PITCH) + boff + 32 * g);
#pragma unroll
                for (int mt = 0; mt < 2; ++mt) {
                    mma16816(acc[mt][np * 2],     a[mt], b0, b1);
                    mma16816(acc[mt][np * 2 + 1], a[mt], b2, b3);
                }
            }
        }
        __syncthreads();   // all reads of the 4 tiles done before next issue
    }

    if (MODE == 1) {
        const bool odd = (lane & 1);
        const int er   = lane >> 2;
        const int esub = (lane >> 1) & 1;
#pragma unroll
        for (int mt = 0; mt < 2; ++mt) {
            const int m = bm + wM + mt * 16 + er + (odd ? 8 : 0);
            const bool act = (t < lengths[m]);
#pragma unroll
            for (int nt = 0; nt < 8; ++nt) {
                float c0 = acc[mt][nt][0], c1 = acc[mt][nt][1];
                float c2 = acc[mt][nt][2], c3 = acc[mt][nt][3];
                const float x0 = __shfl_xor_sync(0xffffffffu, c0, 1);
                const float x1 = __shfl_xor_sync(0xffffffffu, c1, 1);
                const float x2 = __shfl_xor_sync(0xffffffffu, c2, 1);
                const float x3 = __shfl_xor_sync(0xffffffffu, c3, 1);
                const float gi = odd ? x2 : c0;
                const float gf = odd ? x3 : c1;
                const float gg = odd ? c2 : x0;
                const float go = odd ? c3 : x1;

                const int e_local = (wid >> 2) * 16 + nt * 2 + esub;
                const size_t off = (size_t)m * 256 + bn * 32 + e_local;
                if (act) {
                    const float4 bb = *reinterpret_cast<const float4*>(&bs[4 * e_local]);
                    float cc = Cs[off];
                    cc = fsig(gf + bb.y) * cc + fsig(gi + bb.x) * ftanh_(gg + bb.z);
                    Cs[off] = cc;
                    const float h = fsig(go + bb.w) * ftanh_(cc);
                    const __nv_bfloat16 bh = __float2bfloat16_rn(h);
                    Hwh[off] = __bfloat16_as_ushort(bh);
                    Hwl[off] = __bfloat16_as_ushort(
                        __float2bfloat16_rn(h - __bfloat162float(bh)));
                } else {
                    Hwh[off] = Hh[off];
                    Hwl[off] = Hl[off];
                }
            }
        }
    } else {
        const int er = lane >> 2;
        const int cb = 2 * (lane & 3);
#pragma unroll
        for (int mt = 0; mt < 2; ++mt) {
            const int m = bm + wM + mt * 16 + er;
#pragma unroll
            for (int nt = 0; nt < 8; ++nt) {
                const int col = bn * 128 + wN + nt * 8 + cb;
                *reinterpret_cast<float2*>(Gout + (size_t)m * GATES + col) =
                    make_float2(acc[mt][nt][0], acc[mt][nt][1]);
                *reinterpret_cast<float2*>(Gout + (size_t)(m + 8) * GATES + col) =
                    make_float2(acc[mt][nt][2], acc[mt][nt][3]);
            }
        }
    }
}

// ---------------------------------------------------------------------------
// Serial instruction LSTM — R5/R12 structure verbatim (best measured).
// ---------------------------------------------------------------------------
__global__ void __launch_bounds__(512, 1) __cluster_dims__(NCLUS, 1, 1)
ins_lstm(const float* __restrict__ G,
         const float* __restrict__ Whh,
         const float* __restrict__ bih,
         const float* __restrict__ bhh,
         const float* __restrict__ Wl,
         float* __restrict__ part)
{
    __shared__ __align__(16) float hbuf[2][272];
    __shared__ float gs[128];
    __shared__ __align__(8) unsigned long long bar2[2];

    const int tid = threadIdx.x;
    const int cta = blockIdx.x;
    const int r   = tid >> 2;
    const int q   = tid & 3;
    const int grow = (r >> 5) * 256 + cta * 32 + (r & 31);

    unsigned long long w2[32];
#pragma unroll
    for (int jj = 0; jj < 16; ++jj) {
        const float4 v = *reinterpret_cast<const float4*>(
            Whh + (size_t)grow * 256 + q * 64 + jj * 4);
        asm("mov.b64 %0, {%1, %2};" : "=l"(w2[2 * jj])
            : "r"(__float_as_uint(v.x)), "r"(__float_as_uint(v.y)));
        asm("mov.b64 %0, {%1, %2};" : "=l"(w2[2 * jj + 1])
            : "r"(__float_as_uint(v.z)), "r"(__float_as_uint(v.w)));
    }
    const float brow = bih[grow] + bhh[grow];
    const float wl = (tid < 32) ? Wl[cta * 32 + tid] : 0.0f;
    float cst = 0.0f;

    for (int i = tid; i < 2 * 272; i += 512)
        (&hbuf[0][0])[i] = 0.0f;

    const uint32_t hbase = (uint32_t)__cvta_generic_to_shared(&hbuf[0][0]);
    const uint32_t bbase = (uint32_t)__cvta_generic_to_shared(&bar2[0]);

    if (tid == 0) {
        asm volatile("mbarrier.init.shared.b64 [%0], 1;" :: "r"(bbase) : "memory");
        asm volatile("mbarrier.init.shared.b64 [%0], 1;" :: "r"(bbase + 8) : "memory");
        asm volatile("mbarrier.arrive.expect_tx.shared.b64 _, [%0], 1024;"
                     :: "r"(bbase) : "memory");
        asm volatile("mbarrier.arrive.expect_tx.shared.b64 _, [%0], 1024;"
                     :: "r"(bbase + 8) : "memory");
    }

    uint32_t rh[NCLUS], rb[NCLUS];
    {
        const uint32_t coff = (uint32_t)(((cta >> 1) * 68 + (cta & 1) * 32) * 4
                                         + (tid & 15) * 8);
#pragma unroll
        for (int j = 0; j < NCLUS; ++j) {
            uint32_t a, b;
            asm("mapa.shared::cluster.u32 %0, %1, %2;" : "=r"(a) : "r"(hbase), "r"(j));
            asm("mapa.shared::cluster.u32 %0, %1, %2;" : "=r"(b) : "r"(bbase), "r"(j));
            rh[j] = a + coff;
            rb[j] = b;
        }
    }

    __syncthreads();
    asm volatile("barrier.cluster.arrive.aligned;" ::: "memory");
    asm volatile("barrier.cluster.wait.aligned;" ::: "memory");

    float gp0 = 0.0f, gp1 = 0.0f;
    if (q == 0) {
        gp0 = __ldg(&G[grow]);
        gp1 = __ldg(&G[GATES + grow]);
    }

    int php0 = 0, php1 = 0;
    for (int s = 0; s < N_INS; ++s) {
        const int p = s & 1;

        if (s > 0) {
            const uint32_t ba = bbase + (uint32_t)(p * 8);
            const int phx = p ? php1 : php0;
            MBAR_WAIT(ba, phx);
            if (p) php1 ^= 1; else php0 ^= 1;
            if (tid == 0)
                asm volatile("mbarrier.arrive.expect_tx.shared.b64 _, [%0], 1024;"
                             :: "r"(ba) : "memory");
        }

        float gn = 0.0f;
        if (q == 0) {
            const int sn = (s + 2 < N_INS) ? s + 2 : N_INS - 1;
            gn = __ldg(&G[(size_t)sn * GATES + grow]);
        }

        const ulonglong2* hp = reinterpret_cast<const ulonglong2*>(&hbuf[p][q * 68]);
        unsigned long long a2 = 0ULL, b2 = 0ULL;
#pragma unroll
        for (int jj = 0; jj < 16; ++jj) {
            const ulonglong2 hv = hp[jj];
            FMA2(a2, w2[2 * jj],     hv.x);
            FMA2(b2, w2[2 * jj + 1], hv.y);
        }
        float s0, s1, s2, s3;
        UNPACK2(s0, s1, a2);
        UNPACK2(s2, s3, b2);
        float acc = (s0 + s1) + (s2 + s3);
        acc += __shfl_xor_sync(0xffffffffu, acc, 1);
        acc += __shfl_xor_sync(0xffffffffu, acc, 2);
        if (q == 0) gs[r] = acc + gp0 + brow;
        gp0 = gp1; gp1 = gn;
        __syncthreads();

        if (tid < 32) {
            const float gi = gs[tid];
            const float gf = gs[32 + tid];
            const float gg = gs[64 + tid];
            const float go = gs[96 + tid];
            cst = fsig(gf) * cst + fsig(gi) * ftanh_(gg);
            const float h = fsig(go) * ftanh_(cst);

            const float hlo = __shfl_sync(0xffffffffu, h, (tid & 15) * 2);
            const float hhi = __shfl_sync(0xffffffffu, h, (tid & 15) * 2 + 1);
            if (tid < 16 && s + 1 < N_INS) {
                unsigned long long pkt;
                asm("mov.b64 %0, {%1, %2};" : "=l"(pkt)
                    : "r"(__float_as_uint(hlo)), "r"(__float_as_uint(hhi)));
                const uint32_t bufo = (uint32_t)((p ^ 1) * 272 * 4);
                const uint32_t baro = (uint32_t)((p ^ 1) * 8);
#pragma unroll
                for (int j = 0; j < NCLUS; ++j) {
                    asm volatile(
                        "st.async.shared::cluster.mbarrier::complete_tx::bytes.b64 "
                        "[%0], %1, [%2];"
                        :: "r"(rh[j] + bufo), "l"(pkt), "r"(rb[j] + baro)
                        : "memory");
                }
            }

            float pp = h * wl;
#pragma unroll
            for (int o = 16; o > 0; o >>= 1)
                pp += __shfl_xor_sync(0xffffffffu, pp, o);
            if (tid == 0) part[(size_t)cta * N_INS + s] = pp;
        }
    }
}

__global__ void __launch_bounds__(256)
finalize(float* __restrict__ out, const float* __restrict__ part,
         const float* __restrict__ bl)
{
    const int n = blockIdx.x * 256 + threadIdx.x;
    float s = bl[0];
#pragma unroll
    for (int k = 0; k < NCLUS; ++k) s += part[(size_t)k * N_INS + n];
    out[n] = s;
}

extern "C" void kernel_launch(void* const* d_in, const int* in_sizes, int n_in,
                              void* d_out, int out_size)
{
    const float* tokens = (const float*)d_in[0];
    const int*   lengths= (const int*)  d_in[1];
    const float* Wih_t  = (const float*)d_in[2];
    const float* Whh_t  = (const float*)d_in[3];
    const float* bih_t  = (const float*)d_in[4];
    const float* bhh_t  = (const float*)d_in[5];
    const float* Wih_i  = (const float*)d_in[6];
    const float* Whh_i  = (const float*)d_in[7];
    const float* bih_i  = (const float*)d_in[8];
    const float* bhh_i  = (const float*)d_in[9];
    const float* Wl     = (const float*)d_in[10];
    const float* bl     = (const float*)d_in[11];
    float* out = (float*)d_out;

    unsigned short *Tbh, *Tbl, *W0h, *W0l, *W1h, *W1l, *W2h, *W2l, *Hh, *Hl;
    float *C, *G, *part;
    cudaGetSymbolAddress((void**)&Tbh, g_Tbh);
    cudaGetSymbolAddress((void**)&Tbl, g_Tbl);
    cudaGetSymbolAddress((void**)&W0h, g_W0h);
    cudaGetSymbolAddress((void**)&W0l, g_W0l);
    cudaGetSymbolAddress((void**)&W1h, g_W1h);
    cudaGetSymbolAddress((void**)&W1l, g_W1l);
    cudaGetSymbolAddress((void**)&W2h, g_W2h);
    cudaGetSymbolAddress((void**)&W2l, g_W2l);
    cudaGetSymbolAddress((void**)&Hh,  g_Hh);
    cudaGetSymbolAddress((void**)&Hl,  g_Hl);
    cudaGetSymbolAddress((void**)&C,   g_C);
    cudaGetSymbolAddress((void**)&G,   g_G);
    cudaGetSymbolAddress((void**)&part, g_part);

    cudaFuncSetAttribute(gemm_mma<1>, cudaFuncAttributeMaxDynamicSharedMemorySize, SMEM_SZ);
    cudaFuncSetAttribute(gemm_mma<0>, cudaFuncAttributeMaxDynamicSharedMemorySize, SMEM_SZ);

    const size_t NH = (size_t)N_INS * HID;
    cudaMemsetAsync(C, 0, NH * sizeof(float));
    cudaMemsetAsync(Hh, 0, NH * sizeof(unsigned short));
    cudaMemsetAsync(Hl, 0, NH * sizeof(unsigned short));

    conv_pair<<<(N_INS * T_MAX * HID / 4 + 255) / 256, 256>>>(
        tokens, Tbh, Tbl, N_INS * T_MAX * HID / 4);
    conv_pair<<<(GATES * HID / 4 + 255) / 256, 256>>>(Wih_t, W0h, W0l, GATES * HID / 4);
    conv_pair<<<(GATES * HID / 4 + 255) / 256, 256>>>(Whh_t, W1h, W1l, GATES * HID / 4);
    conv_pair<<<(GATES * HID / 4 + 255) / 256, 256>>>(Wih_i, W2h, W2l, GATES * HID / 4);

    dim3 grid(N_INS / 128, 8);

    for (int t = 0; t < T_MAX; ++t) {
        unsigned short* hrh = Hh + (size_t)(t & 1) * NH;
        unsigned short* hrl = Hl + (size_t)(t & 1) * NH;
        unsigned short* hwh = Hh + (size_t)((t & 1) ^ 1) * NH;
        unsigned short* hwl = Hl + (size_t)((t & 1) ^ 1) * NH;
        gemm_mma<1><<<grid, 256, SMEM_SZ>>>(Tbh + (size_t)t * HID, Tbl + (size_t)t * HID,
                                            hrh, hrl, W0h, W0l, W1h, W1l,
                                            lengths, bih_t, bhh_t,
                                            hwh, hwl, C, nullptr, t);
    }
    // final H in buffer 0
    gemm_mma<0><<<grid, 256, SMEM_SZ>>>(nullptr, nullptr, Hh, Hl,
                                        W2h, W2l, nullptr, nullptr,
                                        nullptr, nullptr, nullptr,
                                        nullptr, nullptr, nullptr, G, 0);

    ins_lstm<<<NCLUS, 512>>>(G, Whh_i, bih_i, bhh_i, Wl, part);
    finalize<<<N_INS / 256, 256>>>(out, part, bl);
}